// round 1
// baseline (speedup 1.0000x reference)
#include <cuda_runtime.h>
#include <math.h>

#define BN 16
#define LL 1024
#define DD 512
#define FF 2048
#define NEGV (-1000000000.0f)
#define EPSV 1e-6f
#define SMS 132   // padded shared stride (128 + 4), keeps 16B alignment

// ---------------- scratch (static device globals; no allocation) ------------
__device__ float    g_h   [BN * LL * DD];            // LN1 output          33.5 MB
__device__ float    g_sc  [(size_t)BN * LL * LL];    // scores / probs      67 MB
__device__ float    g_x1  [BN * LL * DD];            // post-attention x    33.5 MB
__device__ float    g_h2  [BN * LL * DD];            // LN2 output          33.5 MB
__device__ float    g_f1  [(size_t)BN * LL * FF];    // FFN hidden          134 MB
__device__ unsigned g_maxes[2 * BN];                 // per-batch max of t_m / g_m

// ---------------- GEMM core: 128x128 tile, K-step 8, 256 threads ------------
// BT=true : C = A * B^T  (A:[M,K] rowmajor, B:[N,K] rowmajor) -- QK^T
// BT=false: C = A * B    (A:[M,K] rowmajor, B:[K,N] rowmajor) -- PV / FFN
template <bool BT>
__device__ __forceinline__ void gemm_core(
    const float* __restrict__ A, int lda,
    const float* __restrict__ Bp, int ldb,
    int K, float acc[8][8], float* As, float* Bs)
{
    const int tid = threadIdx.x;
    const int rm  = (tid / 16) * 8;   // compute row base in tile
    const int cn  = (tid % 16) * 8;   // compute col base in tile
    const int am  = tid >> 1;         // loader row (A / B^T)
    const int ak4 = (tid & 1) * 4;    // loader k4
    const int bk  = tid >> 5;         // loader k   (B NN)
    const int bn  = (tid & 31) * 4;   // loader n4  (B NN)

    for (int kt = 0; kt < K; kt += 8) {
        __syncthreads();
        {
            float4 av = *(const float4*)(A + (size_t)am * lda + kt + ak4);
            As[(ak4 + 0) * SMS + am] = av.x;
            As[(ak4 + 1) * SMS + am] = av.y;
            As[(ak4 + 2) * SMS + am] = av.z;
            As[(ak4 + 3) * SMS + am] = av.w;
        }
        if (BT) {
            float4 bv = *(const float4*)(Bp + (size_t)am * ldb + kt + ak4);
            Bs[(ak4 + 0) * SMS + am] = bv.x;
            Bs[(ak4 + 1) * SMS + am] = bv.y;
            Bs[(ak4 + 2) * SMS + am] = bv.z;
            Bs[(ak4 + 3) * SMS + am] = bv.w;
        } else {
            float4 bv = *(const float4*)(Bp + (size_t)(kt + bk) * ldb + bn);
            *(float4*)(Bs + bk * SMS + bn) = bv;
        }
        __syncthreads();

        #pragma unroll
        for (int kk = 0; kk < 8; kk++) {
            float4 a0 = *(const float4*)(As + kk * SMS + rm);
            float4 a1 = *(const float4*)(As + kk * SMS + rm + 4);
            float4 b0 = *(const float4*)(Bs + kk * SMS + cn);
            float4 b1 = *(const float4*)(Bs + kk * SMS + cn + 4);
            float a[8] = {a0.x, a0.y, a0.z, a0.w, a1.x, a1.y, a1.z, a1.w};
            float b[8] = {b0.x, b0.y, b0.z, b0.w, b1.x, b1.y, b1.z, b1.w};
            #pragma unroll
            for (int i = 0; i < 8; i++)
                #pragma unroll
                for (int j = 0; j < 8; j++)
                    acc[i][j] = fmaf(a[i], b[j], acc[i][j]);
        }
    }
}

// ---------------- small kernels ---------------------------------------------
__global__ void init_max_kernel()
{
    if (threadIdx.x < 2 * BN) g_maxes[threadIdx.x] = 0u;
}

// per-batch max over L*L entries of t_m and g_m (all values >= 0 -> uint max ok)
__global__ void max_kernel(const float* __restrict__ t_m,
                           const float* __restrict__ g_m)
{
    const int seg = blockIdx.x;        // 0..15
    const int b   = blockIdx.y;        // 0..15
    const int z   = blockIdx.z;        // 0: t_m, 1: g_m
    const float4* src = (const float4*)((z ? g_m : t_m)
                        + (size_t)b * LL * LL + (size_t)seg * (LL * LL / 16));
    const int n4 = (LL * LL / 16) / 4; // 16384 float4 per block
    float mx = 0.0f;
    for (int i = threadIdx.x; i < n4; i += 256) {
        float4 v = src[i];
        mx = fmaxf(mx, fmaxf(fmaxf(v.x, v.y), fmaxf(v.z, v.w)));
    }
    #pragma unroll
    for (int o = 16; o; o >>= 1) mx = fmaxf(mx, __shfl_xor_sync(~0u, mx, o));
    if ((threadIdx.x & 31) == 0)
        atomicMax(&g_maxes[z * BN + b], __float_as_uint(mx));
}

// LayerNorm: one row (512) per block, 128 threads x float4
__global__ void ln_kernel(const float* __restrict__ in,
                          const float* __restrict__ w,
                          const float* __restrict__ bb,
                          float* __restrict__ out)
{
    __shared__ float red[8];
    const size_t base = (size_t)blockIdx.x * DD;
    const int t = threadIdx.x;
    float4 v = ((const float4*)(in + base))[t];
    float s  = v.x + v.y + v.z + v.w;
    float sq = v.x * v.x + v.y * v.y + v.z * v.z + v.w * v.w;
    #pragma unroll
    for (int o = 16; o; o >>= 1) {
        s  += __shfl_xor_sync(~0u, s,  o);
        sq += __shfl_xor_sync(~0u, sq, o);
    }
    const int wid = t >> 5;
    if ((t & 31) == 0) { red[wid] = s; red[4 + wid] = sq; }
    __syncthreads();
    if (t == 0) {
        float S = red[0] + red[1] + red[2] + red[3];
        float Q = red[4] + red[5] + red[6] + red[7];
        float mu  = S * (1.0f / DD);
        float var = Q * (1.0f / DD) - mu * mu;
        red[0] = mu;
        red[1] = 1.0f / sqrtf(var + EPSV);
    }
    __syncthreads();
    const float mu = red[0], inv = red[1];
    float4 wv = ((const float4*)w)[t];
    float4 bv = ((const float4*)bb)[t];
    float4 o;
    o.x = (v.x - mu) * inv * wv.x + bv.x;
    o.y = (v.y - mu) * inv * wv.y + bv.y;
    o.z = (v.z - mu) * inv * wv.z + bv.z;
    o.w = (v.w - mu) * inv * wv.w + bv.w;
    ((float4*)(out + base))[t] = o;
}

// row softmax over 1024 entries, one row per block, 256 threads x float4
__global__ void softmax_kernel(float* __restrict__ s)
{
    __shared__ float red[8];
    const size_t base = (size_t)blockIdx.x * LL;
    const int t = threadIdx.x;
    const int wid = t >> 5;
    float4 v = ((const float4*)(s + base))[t];
    float mx = fmaxf(fmaxf(v.x, v.y), fmaxf(v.z, v.w));
    #pragma unroll
    for (int o = 16; o; o >>= 1) mx = fmaxf(mx, __shfl_xor_sync(~0u, mx, o));
    if ((t & 31) == 0) red[wid] = mx;
    __syncthreads();
    if (t == 0) {
        float m = red[0];
        #pragma unroll
        for (int i = 1; i < 8; i++) m = fmaxf(m, red[i]);
        red[0] = m;
    }
    __syncthreads();
    const float rm = red[0];
    __syncthreads();   // everyone has read red[0] before reuse
    float4 e;
    e.x = expf(v.x - rm); e.y = expf(v.y - rm);
    e.z = expf(v.z - rm); e.w = expf(v.w - rm);
    float ss = e.x + e.y + e.z + e.w;
    #pragma unroll
    for (int o = 16; o; o >>= 1) ss += __shfl_xor_sync(~0u, ss, o);
    if ((t & 31) == 0) red[wid] = ss;
    __syncthreads();
    if (t == 0) {
        float S = 0.0f;
        #pragma unroll
        for (int i = 0; i < 8; i++) S += red[i];
        red[0] = 1.0f / S;
    }
    __syncthreads();
    const float inv = red[0];
    e.x *= inv; e.y *= inv; e.z *= inv; e.w *= inv;
    ((float4*)(s + base))[t] = e;
}

// ---------------- GEMM kernels with fused epilogues -------------------------

// scores = h @ h^T / d + |t_m - max_t| + |g_m - max_g|, masked
__global__ __launch_bounds__(256, 2)
void qk_kernel(const float* __restrict__ t_m, const float* __restrict__ g_m,
               const int* __restrict__ mask)
{
    __shared__ float sm[2 * 8 * SMS];
    const int b  = blockIdx.z;
    const int m0 = blockIdx.y * 128, n0 = blockIdx.x * 128;
    const float* hb = g_h + (size_t)b * LL * DD;
    float acc[8][8] = {};
    gemm_core<true>(hb + (size_t)m0 * DD, DD,
                    hb + (size_t)n0 * DD, DD, DD, acc, sm, sm + 8 * SMS);

    const float mxt = __uint_as_float(g_maxes[b]);
    const float mxg = __uint_as_float(g_maxes[BN + b]);
    const int ty = threadIdx.x / 16, tx = threadIdx.x % 16;
    const size_t base = (size_t)b * LL * LL;
    #pragma unroll
    for (int i = 0; i < 8; i++) {
        const size_t rb = base + (size_t)(m0 + ty * 8 + i) * LL;
        #pragma unroll
        for (int j4 = 0; j4 < 2; j4++) {
            const int col = n0 + tx * 8 + j4 * 4;
            float4 t4 = *(const float4*)(t_m + rb + col);
            float4 g4 = *(const float4*)(g_m + rb + col);
            int4   mk = *(const int4*)(mask + rb + col);
            float4 o;
            o.x = acc[i][j4*4+0] * (1.0f/DD) + fabsf(t4.x - mxt) + fabsf(g4.x - mxg);
            o.y = acc[i][j4*4+1] * (1.0f/DD) + fabsf(t4.y - mxt) + fabsf(g4.y - mxg);
            o.z = acc[i][j4*4+2] * (1.0f/DD) + fabsf(t4.z - mxt) + fabsf(g4.z - mxg);
            o.w = acc[i][j4*4+3] * (1.0f/DD) + fabsf(t4.w - mxt) + fabsf(g4.w - mxg);
            if (mk.x == 0) o.x = NEGV;
            if (mk.y == 0) o.y = NEGV;
            if (mk.z == 0) o.z = NEGV;
            if (mk.w == 0) o.w = NEGV;
            *(float4*)(g_sc + rb + col) = o;
        }
    }
}

// x1 = x + p @ h
__global__ __launch_bounds__(256, 2)
void pv_kernel(const float* __restrict__ x)
{
    __shared__ float sm[2 * 8 * SMS];
    const int b  = blockIdx.z;
    const int m0 = blockIdx.y * 128, n0 = blockIdx.x * 128;
    float acc[8][8] = {};
    gemm_core<false>(g_sc + (size_t)b * LL * LL + (size_t)m0 * LL, LL,
                     g_h  + (size_t)b * LL * DD + n0, DD, LL, acc, sm, sm + 8 * SMS);
    const int ty = threadIdx.x / 16, tx = threadIdx.x % 16;
    const size_t base = (size_t)b * LL * DD;
    #pragma unroll
    for (int i = 0; i < 8; i++) {
        const size_t rb = base + (size_t)(m0 + ty * 8 + i) * DD;
        #pragma unroll
        for (int j4 = 0; j4 < 2; j4++) {
            const int col = n0 + tx * 8 + j4 * 4;
            float4 xv = *(const float4*)(x + rb + col);
            float4 o;
            o.x = acc[i][j4*4+0] + xv.x;
            o.y = acc[i][j4*4+1] + xv.y;
            o.z = acc[i][j4*4+2] + xv.z;
            o.w = acc[i][j4*4+3] + xv.w;
            *(float4*)(g_x1 + rb + col) = o;
        }
    }
}

// f1 = relu(h2 @ w1 + b1)
__global__ __launch_bounds__(256, 2)
void ffn1_kernel(const float* __restrict__ w1, const float* __restrict__ b1)
{
    __shared__ float sm[2 * 8 * SMS];
    const int m0 = blockIdx.y * 128, n0 = blockIdx.x * 128;
    float acc[8][8] = {};
    gemm_core<false>(g_h2 + (size_t)m0 * DD, DD, w1 + n0, FF, DD,
                     acc, sm, sm + 8 * SMS);
    const int ty = threadIdx.x / 16, tx = threadIdx.x % 16;
    #pragma unroll
    for (int i = 0; i < 8; i++) {
        const size_t rb = (size_t)(m0 + ty * 8 + i) * FF;
        #pragma unroll
        for (int j4 = 0; j4 < 2; j4++) {
            const int col = n0 + tx * 8 + j4 * 4;
            float4 bv = *(const float4*)(b1 + col);
            float4 o;
            o.x = fmaxf(acc[i][j4*4+0] + bv.x, 0.0f);
            o.y = fmaxf(acc[i][j4*4+1] + bv.y, 0.0f);
            o.z = fmaxf(acc[i][j4*4+2] + bv.z, 0.0f);
            o.w = fmaxf(acc[i][j4*4+3] + bv.w, 0.0f);
            *(float4*)(g_f1 + rb + col) = o;
        }
    }
}

// out = (x1 + f1 @ w2 + b2) / d
__global__ __launch_bounds__(256, 2)
void ffn2_kernel(const float* __restrict__ w2, const float* __restrict__ b2,
                 float* __restrict__ out)
{
    __shared__ float sm[2 * 8 * SMS];
    const int m0 = blockIdx.y * 128, n0 = blockIdx.x * 128;
    float acc[8][8] = {};
    gemm_core<false>(g_f1 + (size_t)m0 * FF, FF, w2 + n0, DD, FF,
                     acc, sm, sm + 8 * SMS);
    const int ty = threadIdx.x / 16, tx = threadIdx.x % 16;
    #pragma unroll
    for (int i = 0; i < 8; i++) {
        const size_t rb = (size_t)(m0 + ty * 8 + i) * DD;
        #pragma unroll
        for (int j4 = 0; j4 < 2; j4++) {
            const int col = n0 + tx * 8 + j4 * 4;
            float4 bv = *(const float4*)(b2 + col);
            float4 xv = *(const float4*)(g_x1 + rb + col);
            float4 o;
            o.x = (xv.x + acc[i][j4*4+0] + bv.x) * (1.0f / DD);
            o.y = (xv.y + acc[i][j4*4+1] + bv.y) * (1.0f / DD);
            o.z = (xv.z + acc[i][j4*4+2] + bv.z) * (1.0f / DD);
            o.w = (xv.w + acc[i][j4*4+3] + bv.w) * (1.0f / DD);
            *(float4*)(out + rb + col) = o;
        }
    }
}

// ---------------- launch ----------------------------------------------------
extern "C" void kernel_launch(void* const* d_in, const int* in_sizes, int n_in,
                              void* d_out, int out_size)
{
    const float* x    = (const float*)d_in[0];
    const float* t_m  = (const float*)d_in[1];
    const float* g_mm = (const float*)d_in[2];
    const int*   mask = (const int*)  d_in[3];
    const float* ln1w = (const float*)d_in[4];
    const float* ln1b = (const float*)d_in[5];
    const float* ln2w = (const float*)d_in[6];
    const float* ln2b = (const float*)d_in[7];
    const float* w1   = (const float*)d_in[8];
    const float* b1   = (const float*)d_in[9];
    const float* w2   = (const float*)d_in[10];
    const float* b2   = (const float*)d_in[11];
    float* out = (float*)d_out;

    float *ph, *ph2, *px1;
    cudaGetSymbolAddress((void**)&ph,  g_h);
    cudaGetSymbolAddress((void**)&ph2, g_h2);
    cudaGetSymbolAddress((void**)&px1, g_x1);

    init_max_kernel<<<1, 32>>>();
    ln_kernel<<<BN * LL, 128>>>(x, ln1w, ln1b, ph);
    max_kernel<<<dim3(16, BN, 2), 256>>>(t_m, g_mm);
    qk_kernel<<<dim3(8, 8, BN), 256>>>(t_m, g_mm, mask);
    softmax_kernel<<<BN * LL, 256>>>( // operates in place on g_sc
        [] { float* p; cudaGetSymbolAddress((void**)&p, g_sc); return p; }());
    pv_kernel<<<dim3(4, 8, BN), 256>>>(x);
    ln_kernel<<<BN * LL, 128>>>(px1, ln2w, ln2b, ph2);
    ffn1_kernel<<<dim3(FF / 128, BN * LL / 128), 256>>>(w1, b1);
    ffn2_kernel<<<dim3(DD / 128, BN * LL / 128), 256>>>(w2, b2, out);
}

// round 4
// speedup vs baseline: 3.1960x; 3.1960x over previous
#include <cuda_runtime.h>
#include <math.h>
#include <stdint.h>

#define BN 16
#define LL 1024
#define DD 512
#define FF 2048
#define NEGV (-1000000000.0f)
#define EPSV 1e-6f

// ---- mma.sync tf32 GEMM tiling ----
#define BM 128
#define BNT 128
#define BK 32
#define AST 36                       // smem row stride in floats (pad 4)
#define ASZ (128 * AST)              // one stage of one operand, floats
#define SMEM_DYN (4 * ASZ * 4)       // 2 stages x (A + B) = 73728 bytes

// ---------------- scratch ----------------------------------------------------
__device__ float    g_h  [BN*LL*DD];
__device__ float    g_hT [BN*LL*DD];
__device__ float    g_sc [(size_t)BN*LL*LL];
__device__ float    g_x1 [BN*LL*DD];
__device__ float    g_h2 [BN*LL*DD];
__device__ float    g_f1 [(size_t)BN*LL*FF];
__device__ float    g_w1T[FF*DD];
__device__ float    g_w2T[DD*FF];
__device__ unsigned g_maxes[2*BN];

// ---------------- helpers -----------------------------------------------------
__device__ __forceinline__ uint32_t smem_u32(const void* p) {
    uint32_t a;
    asm("{ .reg .u64 t; cvta.to.shared.u64 t, %1; cvt.u32.u64 %0, t; }" : "=r"(a) : "l"(p));
    return a;
}
__device__ __forceinline__ float tf32r(float x) {
    uint32_t u;
    asm("cvt.rn.tf32.f32 %0, %1;" : "=r"(u) : "f"(x));
    return __uint_as_float(u);
}
#define CP16(s, g) \
    asm volatile("cp.async.cg.shared.global [%0], [%1], 16;" :: "r"(s), "l"(g))
#define CPCOMMIT() asm volatile("cp.async.commit_group;" ::: "memory")
#define CPWAIT(n)  asm volatile("cp.async.wait_group %0;" :: "n"(n) : "memory")

#define MMA8(c, a, b) \
    asm volatile("mma.sync.aligned.m16n8k8.row.col.f32.tf32.tf32.f32 " \
        "{%0,%1,%2,%3}, {%4,%5,%6,%7}, {%8,%9}, {%0,%1,%2,%3};" \
        : "+f"((c)[0]), "+f"((c)[1]), "+f"((c)[2]), "+f"((c)[3]) \
        : "r"((a)[0]), "r"((a)[1]), "r"((a)[2]), "r"((a)[3]), \
          "r"((b)[0]), "r"((b)[1]))

// ---------------- mma core: acc[4][4][4] = A[128,K] * B[128,K]^T tile ---------
// A row-major [M,K] (lda), B K-major [N,K] (ldb). 256 threads, warps 2x4.
__device__ __forceinline__ void mma_core(
    const float* __restrict__ A, int lda,
    const float* __restrict__ B, int ldb,
    int K, float acc[4][4][4], float* smem)
{
    const int tid  = threadIdx.x;
    const int lane = tid & 31;
    const int wid  = tid >> 5;
    const int wr   = wid >> 2;       // 0..1
    const int wc   = wid & 3;        // 0..3
    const int lr   = tid >> 3;       // loader row 0..31
    const int lc   = (tid & 7) * 4;  // loader col 0,4,..,28

    float* As = smem;                // 2 stages
    float* Bs = smem + 2 * ASZ;      // 2 stages
    const uint32_t sa = smem_u32(As) + ((lr * AST + lc) << 2);
    const uint32_t sb = smem_u32(Bs) + ((lr * AST + lc) << 2);
    const float* gA = A + (size_t)lr * lda + lc;
    const float* gB = B + (size_t)lr * ldb + lc;
    const int nk = K / BK;

    // prefetch stage 0
    {
        #pragma unroll
        for (int i = 0; i < 4; i++) {
            CP16(sa + i * (32 * AST * 4), gA + (size_t)(i * 32) * lda);
            CP16(sb + i * (32 * AST * 4), gB + (size_t)(i * 32) * ldb);
        }
        CPCOMMIT();
    }

    for (int kt = 0; kt < nk; kt++) {
        if (kt + 1 < nk) {
            const uint32_t so = (uint32_t)(((kt + 1) & 1) * ASZ * 4);
            const int ko = (kt + 1) * BK;
            #pragma unroll
            for (int i = 0; i < 4; i++) {
                CP16(sa + so + i * (32 * AST * 4), gA + (size_t)(i * 32) * lda + ko);
                CP16(sb + so + i * (32 * AST * 4), gB + (size_t)(i * 32) * ldb + ko);
            }
            CPCOMMIT();
            CPWAIT(1);
        } else {
            CPWAIT(0);
        }
        __syncthreads();

        const float* as = As + (kt & 1) * ASZ;
        const float* bs = Bs + (kt & 1) * ASZ;
        #pragma unroll
        for (int ks = 0; ks < 4; ks++) {
            uint32_t af[4][4], bf[4][2];
            #pragma unroll
            for (int m = 0; m < 4; m++) {
                const float* p = as + (wr * 64 + m * 16 + (lane >> 2)) * AST
                                    + ks * 8 + (lane & 3);
                af[m][0] = __float_as_uint(p[0]);
                af[m][1] = __float_as_uint(p[8 * AST]);
                af[m][2] = __float_as_uint(p[4]);
                af[m][3] = __float_as_uint(p[8 * AST + 4]);
            }
            #pragma unroll
            for (int n = 0; n < 4; n++) {
                const float* p = bs + (wc * 32 + n * 8 + (lane >> 2)) * AST
                                    + ks * 8 + (lane & 3);
                bf[n][0] = __float_as_uint(p[0]);
                bf[n][1] = __float_as_uint(p[4]);
            }
            #pragma unroll
            for (int m = 0; m < 4; m++)
                #pragma unroll
                for (int n = 0; n < 4; n++)
                    MMA8(acc[m][n], af[m], bf[n]);
        }
        __syncthreads();
    }
}

// accumulator element (m,n) covers rows {r0, r0+8}, cols {c0, c0+1}:
//   r0 = m0 + wr*64 + m*16 + lane>>2, c0 = n0 + wc*32 + n*8 + 2*(lane&3)

// ---------------- GEMM kernels with fused epilogues --------------------------
__global__ __launch_bounds__(256, 2)
void gemm_qk(const float* __restrict__ t_m, const float* __restrict__ g_m,
             const int* __restrict__ mask)
{
    extern __shared__ __align__(16) float smem[];
    const int b = blockIdx.z, m0 = blockIdx.y * BM, n0 = blockIdx.x * BNT;
    const float* hb = g_h + (size_t)b * LL * DD;
    float acc[4][4][4] = {};
    mma_core(hb + (size_t)m0 * DD, DD, hb + (size_t)n0 * DD, DD, DD, acc, smem);

    const int lane = threadIdx.x & 31, wid = threadIdx.x >> 5;
    const int wr = wid >> 2, wc = wid & 3;
    const float mxt = __uint_as_float(g_maxes[b]);
    const float mxg = __uint_as_float(g_maxes[BN + b]);
    const size_t bb = (size_t)b * LL * LL;
    #pragma unroll
    for (int m = 0; m < 4; m++) {
        const int r0 = m0 + wr * 64 + m * 16 + (lane >> 2);
        #pragma unroll
        for (int n = 0; n < 4; n++) {
            const int c0 = n0 + wc * 32 + n * 8 + 2 * (lane & 3);
            #pragma unroll
            for (int h = 0; h < 2; h++) {
                const size_t p = bb + (size_t)(r0 + h * 8) * LL + c0;
                float2 t2 = *(const float2*)(t_m + p);
                float2 g2 = *(const float2*)(g_m + p);
                int2   mk = *(const int2*)(mask + p);
                float2 o;
                o.x = acc[m][n][h*2+0] * (1.0f/DD) + fabsf(t2.x - mxt) + fabsf(g2.x - mxg);
                o.y = acc[m][n][h*2+1] * (1.0f/DD) + fabsf(t2.y - mxt) + fabsf(g2.y - mxg);
                if (mk.x == 0) o.x = NEGV;
                if (mk.y == 0) o.y = NEGV;
                *(float2*)(g_sc + p) = o;
            }
        }
    }
}

__global__ __launch_bounds__(256, 2)
void gemm_pv(const float* __restrict__ x)
{
    extern __shared__ __align__(16) float smem[];
    const int b = blockIdx.z, m0 = blockIdx.y * BM, n0 = blockIdx.x * BNT;
    float acc[4][4][4] = {};
    mma_core(g_sc + (size_t)b * LL * LL + (size_t)m0 * LL, LL,
             g_hT + (size_t)b * LL * DD + (size_t)n0 * LL, LL, LL, acc, smem);

    const int lane = threadIdx.x & 31, wid = threadIdx.x >> 5;
    const int wr = wid >> 2, wc = wid & 3;
    const size_t bb = (size_t)b * LL * DD;
    #pragma unroll
    for (int m = 0; m < 4; m++) {
        const int r0 = m0 + wr * 64 + m * 16 + (lane >> 2);
        #pragma unroll
        for (int n = 0; n < 4; n++) {
            const int c0 = n0 + wc * 32 + n * 8 + 2 * (lane & 3);
            #pragma unroll
            for (int h = 0; h < 2; h++) {
                const size_t p = bb + (size_t)(r0 + h * 8) * DD + c0;
                float2 xv = *(const float2*)(x + p);
                float2 o;
                o.x = acc[m][n][h*2+0] + xv.x;
                o.y = acc[m][n][h*2+1] + xv.y;
                *(float2*)(g_x1 + p) = o;
            }
        }
    }
}

__global__ __launch_bounds__(256, 2)
void gemm_f1(const float* __restrict__ b1)
{
    extern __shared__ __align__(16) float smem[];
    const int m0 = blockIdx.y * BM, n0 = blockIdx.x * BNT;
    float acc[4][4][4] = {};
    mma_core(g_h2 + (size_t)m0 * DD, DD, g_w1T + (size_t)n0 * DD, DD, DD, acc, smem);

    const int lane = threadIdx.x & 31, wid = threadIdx.x >> 5;
    const int wr = wid >> 2, wc = wid & 3;
    #pragma unroll
    for (int m = 0; m < 4; m++) {
        const int r0 = m0 + wr * 64 + m * 16 + (lane >> 2);
        #pragma unroll
        for (int n = 0; n < 4; n++) {
            const int c0 = n0 + wc * 32 + n * 8 + 2 * (lane & 3);
            const float2 bv = *(const float2*)(b1 + c0);
            #pragma unroll
            for (int h = 0; h < 2; h++) {
                const size_t p = (size_t)(r0 + h * 8) * FF + c0;
                float2 o;
                o.x = tf32r(fmaxf(acc[m][n][h*2+0] + bv.x, 0.0f));
                o.y = tf32r(fmaxf(acc[m][n][h*2+1] + bv.y, 0.0f));
                *(float2*)(g_f1 + p) = o;
            }
        }
    }
}

__global__ __launch_bounds__(256, 2)
void gemm_f2(const float* __restrict__ b2, float* __restrict__ out)
{
    extern __shared__ __align__(16) float smem[];
    const int m0 = blockIdx.y * BM, n0 = blockIdx.x * BNT;
    float acc[4][4][4] = {};
    mma_core(g_f1 + (size_t)m0 * FF, FF, g_w2T + (size_t)n0 * FF, FF, FF, acc, smem);

    const int lane = threadIdx.x & 31, wid = threadIdx.x >> 5;
    const int wr = wid >> 2, wc = wid & 3;
    #pragma unroll
    for (int m = 0; m < 4; m++) {
        const int r0 = m0 + wr * 64 + m * 16 + (lane >> 2);
        #pragma unroll
        for (int n = 0; n < 4; n++) {
            const int c0 = n0 + wc * 32 + n * 8 + 2 * (lane & 3);
            const float2 bv = *(const float2*)(b2 + c0);
            #pragma unroll
            for (int h = 0; h < 2; h++) {
                const size_t p = (size_t)(r0 + h * 8) * DD + c0;
                float2 xv = *(const float2*)(g_x1 + p);
                float2 o;
                o.x = (xv.x + acc[m][n][h*2+0] + bv.x) * (1.0f / DD);
                o.y = (xv.y + acc[m][n][h*2+1] + bv.y) * (1.0f / DD);
                *(float2*)(out + p) = o;
            }
        }
    }
}

// ---------------- elementwise kernels ----------------------------------------
__global__ void init_max_kernel()
{
    if (threadIdx.x < 2 * BN) g_maxes[threadIdx.x] = 0u;
}

__global__ void max_kernel(const float* __restrict__ t_m,
                           const float* __restrict__ g_m)
{
    const int seg = blockIdx.x, b = blockIdx.y, z = blockIdx.z;
    const float4* src = (const float4*)((z ? g_m : t_m)
                        + (size_t)b * LL * LL + (size_t)seg * (LL * LL / 16));
    const int n4 = (LL * LL / 16) / 4;
    float mx = 0.0f;
    for (int i = threadIdx.x; i < n4; i += 256) {
        float4 v = src[i];
        mx = fmaxf(mx, fmaxf(fmaxf(v.x, v.y), fmaxf(v.z, v.w)));
    }
    #pragma unroll
    for (int o = 16; o; o >>= 1) mx = fmaxf(mx, __shfl_xor_sync(~0u, mx, o));
    if ((threadIdx.x & 31) == 0)
        atomicMax(&g_maxes[z * BN + b], __float_as_uint(mx));
}

// LayerNorm, output rounded to tf32 (GEMM operand)
__global__ void ln_kernel(const float* __restrict__ in,
                          const float* __restrict__ w,
                          const float* __restrict__ bb,
                          float* __restrict__ out)
{
    __shared__ float red[8];
    const size_t base = (size_t)blockIdx.x * DD;
    const int t = threadIdx.x;
    float4 v = ((const float4*)(in + base))[t];
    float s  = v.x + v.y + v.z + v.w;
    float sq = v.x*v.x + v.y*v.y + v.z*v.z + v.w*v.w;
    #pragma unroll
    for (int o = 16; o; o >>= 1) {
        s  += __shfl_xor_sync(~0u, s,  o);
        sq += __shfl_xor_sync(~0u, sq, o);
    }
    const int wid = t >> 5;
    if ((t & 31) == 0) { red[wid] = s; red[4 + wid] = sq; }
    __syncthreads();
    if (t == 0) {
        float S = red[0] + red[1] + red[2] + red[3];
        float Q = red[4] + red[5] + red[6] + red[7];
        float mu  = S * (1.0f / DD);
        float var = Q * (1.0f / DD) - mu * mu;
        red[0] = mu;
        red[1] = 1.0f / sqrtf(var + EPSV);
    }
    __syncthreads();
    const float mu = red[0], inv = red[1];
    float4 wv = ((const float4*)w)[t];
    float4 bv = ((const float4*)bb)[t];
    float4 o;
    o.x = tf32r((v.x - mu) * inv * wv.x + bv.x);
    o.y = tf32r((v.y - mu) * inv * wv.y + bv.y);
    o.z = tf32r((v.z - mu) * inv * wv.z + bv.z);
    o.w = tf32r((v.w - mu) * inv * wv.w + bv.w);
    ((float4*)(out + base))[t] = o;
}

// row softmax over 1024, output rounded to tf32 (GEMM operand)
__global__ void softmax_kernel(float* __restrict__ s)
{
    __shared__ float red[8];
    const size_t base = (size_t)blockIdx.x * LL;
    const int t = threadIdx.x, wid = t >> 5;
    float4 v = ((const float4*)(s + base))[t];
    float mx = fmaxf(fmaxf(v.x, v.y), fmaxf(v.z, v.w));
    #pragma unroll
    for (int o = 16; o; o >>= 1) mx = fmaxf(mx, __shfl_xor_sync(~0u, mx, o));
    if ((t & 31) == 0) red[wid] = mx;
    __syncthreads();
    if (t == 0) {
        float m = red[0];
        #pragma unroll
        for (int i = 1; i < 8; i++) m = fmaxf(m, red[i]);
        red[0] = m;
    }
    __syncthreads();
    const float rm = red[0];
    __syncthreads();
    float4 e;
    e.x = expf(v.x - rm); e.y = expf(v.y - rm);
    e.z = expf(v.z - rm); e.w = expf(v.w - rm);
    float ss = e.x + e.y + e.z + e.w;
    #pragma unroll
    for (int o = 16; o; o >>= 1) ss += __shfl_xor_sync(~0u, ss, o);
    if ((t & 31) == 0) red[wid] = ss;
    __syncthreads();
    if (t == 0) {
        float S = 0.0f;
        #pragma unroll
        for (int i = 0; i < 8; i++) S += red[i];
        red[0] = 1.0f / S;
    }
    __syncthreads();
    const float inv = red[0];
    e.x = tf32r(e.x * inv); e.y = tf32r(e.y * inv);
    e.z = tf32r(e.z * inv); e.w = tf32r(e.w * inv);
    ((float4*)(s + base))[t] = e;
}

// transpose [R,C] -> [C,R] per batch-z, rounding to tf32
__global__ void trans_kernel(const float* __restrict__ in, float* __restrict__ out,
                             int R, int C)
{
    __shared__ float tile[32][33];
    const int bx = blockIdx.x * 32, by = blockIdx.y * 32;
    const size_t zoff = (size_t)blockIdx.z * R * C;
    const int tx = threadIdx.x, ty = threadIdx.y;
    #pragma unroll
    for (int i = 0; i < 32; i += 8)
        tile[ty + i][tx] = in[zoff + (size_t)(by + ty + i) * C + bx + tx];
    __syncthreads();
    #pragma unroll
    for (int i = 0; i < 32; i += 8)
        out[zoff + (size_t)(bx + ty + i) * R + by + tx] = tf32r(tile[tx][ty + i]);
}

// ---------------- launch ------------------------------------------------------
extern "C" void kernel_launch(void* const* d_in, const int* in_sizes, int n_in,
                              void* d_out, int out_size)
{
    const float* x    = (const float*)d_in[0];
    const float* t_m  = (const float*)d_in[1];
    const float* g_mm = (const float*)d_in[2];
    const int*   mask = (const int*)  d_in[3];
    const float* ln1w = (const float*)d_in[4];
    const float* ln1b = (const float*)d_in[5];
    const float* ln2w = (const float*)d_in[6];
    const float* ln2b = (const float*)d_in[7];
    const float* w1   = (const float*)d_in[8];
    const float* b1   = (const float*)d_in[9];
    const float* w2   = (const float*)d_in[10];
    const float* b2   = (const float*)d_in[11];
    float* out = (float*)d_out;

    cudaFuncSetAttribute(gemm_qk, cudaFuncAttributeMaxDynamicSharedMemorySize, SMEM_DYN);
    cudaFuncSetAttribute(gemm_pv, cudaFuncAttributeMaxDynamicSharedMemorySize, SMEM_DYN);
    cudaFuncSetAttribute(gemm_f1, cudaFuncAttributeMaxDynamicSharedMemorySize, SMEM_DYN);
    cudaFuncSetAttribute(gemm_f2, cudaFuncAttributeMaxDynamicSharedMemorySize, SMEM_DYN);

    float *ph, *phT, *psc, *px1, *ph2, *pw1T, *pw2T;
    cudaGetSymbolAddress((void**)&ph,   g_h);
    cudaGetSymbolAddress((void**)&phT,  g_hT);
    cudaGetSymbolAddress((void**)&psc,  g_sc);
    cudaGetSymbolAddress((void**)&px1,  g_x1);
    cudaGetSymbolAddress((void**)&ph2,  g_h2);
    cudaGetSymbolAddress((void**)&pw1T, g_w1T);
    cudaGetSymbolAddress((void**)&pw2T, g_w2T);

    init_max_kernel<<<1, 32>>>();
    ln_kernel<<<BN * LL, 128>>>(x, ln1w, ln1b, ph);
    max_kernel<<<dim3(16, BN, 2), 256>>>(t_m, g_mm);
    trans_kernel<<<dim3(DD / 32, LL / 32, BN), dim3(32, 8)>>>(ph, phT, LL, DD);
    trans_kernel<<<dim3(FF / 32, DD / 32, 1),  dim3(32, 8)>>>(w1, pw1T, DD, FF);
    trans_kernel<<<dim3(DD / 32, FF / 32, 1),  dim3(32, 8)>>>(w2, pw2T, FF, DD);

    gemm_qk<<<dim3(LL / BNT, LL / BM, BN), 256, SMEM_DYN>>>(t_m, g_mm, mask);
    softmax_kernel<<<BN * LL, 256>>>(psc);
    gemm_pv<<<dim3(DD / BNT, LL / BM, BN), 256, SMEM_DYN>>>(x);
    ln_kernel<<<BN * LL, 128>>>(px1, ln2w, ln2b, ph2);
    gemm_f1<<<dim3(FF / BNT, (BN * LL) / BM, 1), 256, SMEM_DYN>>>(b1);
    gemm_f2<<<dim3(DD / BNT, (BN * LL) / BM, 1), 256, SMEM_DYN>>>(b2, out);
}